// round 15
// baseline (speedup 1.0000x reference)
#include <cuda_runtime.h>
#include <cuda_fp16.h>
#include <cstddef>

#define D_IN  128
#define D_HID 128
#define D_OUT 32
#define NMAX  100000
#define EMAX  1601000
#define CSR_G 296
#define CSR_T 1024
#define NCHUNKMAX 128

// ---------------- static device scratch (no runtime allocation) ----------------
__device__ __half g_x16 [(size_t)NMAX * D_IN];
__device__ __half g_agg1h[(size_t)NMAX * D_HID];
__device__ __half g_h1h [(size_t)NMAX * D_HID];   // pre-BN h1 (fp16)
__device__ __half g_r2h [(size_t)NMAX * 32];
__device__ __half g_t16 [(size_t)NMAX * 32];
__device__ float  g_agg2[(size_t)NMAX * D_OUT];
__device__ double g_stats[320];
__device__ __half g_w1hT [128 * 256];             // [n][k]: k<128 Wrel1, k>=128 Wroot1
__device__ __half g_w2hT [64 * 128];
__device__ int    g_off[NMAX + 8];
__device__ int    g_tile_sums[NCHUNKMAX];
__device__ int    g_bar;                          // persistent-kernel barrier counter (self-resetting)
__device__ int    g_csrc[EMAX];
__device__ int    g_is64;

// ---------------- fp16 MMA helper ----------------
__device__ __forceinline__ void mma_f16(float c[4], const unsigned a[4], const unsigned b[2]) {
    asm volatile(
        "mma.sync.aligned.m16n8k16.row.col.f32.f16.f16.f32 "
        "{%0,%1,%2,%3}, {%4,%5,%6,%7}, {%8,%9}, {%0,%1,%2,%3};"
        : "+f"(c[0]), "+f"(c[1]), "+f"(c[2]), "+f"(c[3])
        : "r"(a[0]), "r"(a[1]), "r"(a[2]), "r"(a[3]), "r"(b[0]), "r"(b[1]));
}

__device__ __forceinline__ int ldcg_i(const int* p) {
    int v;
    asm volatile("ld.global.cg.s32 %0, [%1];" : "=r"(v) : "l"(p));
    return v;
}

// ---------------- side chain: stats zero + x->fp16 + weight prep ----------------
__global__ void __launch_bounds__(256) init_kernel(
    double* stats,
    const float* __restrict__ x, __half* __restrict__ x16, long long nh2,
    const float* __restrict__ Wrel1, const float* __restrict__ Wroot1,
    const float* __restrict__ Wrel2, const float* __restrict__ Wroot2,
    __half* __restrict__ w1hT, __half* __restrict__ w2hT)
{
    long long i = (long long)blockIdx.x * 256 + threadIdx.x;
    long long stride = (long long)gridDim.x * 256;
    for (long long t = i; t < 320; t += stride) stats[t] = 0.0;
    const float2* xf2 = (const float2*)x;
    __half2* xh2 = (__half2*)x16;
    for (long long t = i; t < nh2; t += stride)
        xh2[t] = __float22half2_rn(xf2[t]);
    for (long long t = i; t < 128 * 256; t += stride) {
        int n = (int)(t >> 8), k = (int)(t & 255);
        float v = (k < 128) ? Wrel1[k * 128 + n] : Wroot1[(k - 128) * 128 + n];
        w1hT[t] = __float2half_rn(v);
    }
    for (long long t = i; t < 64 * 128; t += stride) {
        int n = (int)(t >> 7), k = (int)(t & 127);
        float v = (n < 32) ? Wrel2[k * 32 + n] : Wroot2[k * 32 + (n - 32)];
        w2hT[t] = __float2half_rn(v);
    }
}

// ---------------- persistent CSR build: zero + hist + scan + fill, one kernel ----------------
// Grid barriers via monotonic counter; expected = phase * gridDim.x. Last arrival at
// final (non-waiting) arrive resets the counter for the next graph replay.
__device__ __forceinline__ void grid_bar(int expected) {
    __threadfence();
    __syncthreads();
    if (threadIdx.x == 0) {
        atomicAdd(&g_bar, 1);
        while (atomicAdd(&g_bar, 0) < expected) {}
    }
    __syncthreads();
}

__global__ void __launch_bounds__(CSR_T, 2) csr_build_kernel(
    const void* __restrict__ eiv, int E, int* __restrict__ off,
    int* __restrict__ csrc, int N)
{
    __shared__ int swarp[32];
    __shared__ int sbase;
    const int G = gridDim.x;
    const int b = blockIdx.x;
    const int tid = threadIdx.x;
    const int lane = tid & 31, wid = tid >> 5;
    const int gid = b * CSR_T + tid;
    const int TT = G * CSR_T;
    const int nchunk = (E + 3) >> 2;

    // ---- phase 0: zero off + tile_sums; detect dtype ----
    for (int t = gid; t <= N; t += TT) off[t] = 0;
    for (int t = gid; t < NCHUNKMAX; t += TT) g_tile_sums[t] = 0;
    if (b == 0 && tid == 0) {
        const int* p = (const int*)eiv;
        int n = 2 * E;
        int allzero = 1;
        for (int k = 1; k < 256 && k < n; k += 2) {
            if (p[k] != 0) { allzero = 0; break; }
        }
        g_is64 = allzero;
    }
    grid_bar(G);

    const int is64 = ldcg_i(&g_is64);
    const long long* p64 = (const long long*)eiv;
    const int* p32 = (const int*)eiv;

    // ---- phase 1: histogram (dst only), 4-edge chunks ----
    for (int c = gid; c < nchunk; c += TT) {
        int e0 = c << 2;
        int d[4];
#pragma unroll
        for (int q = 0; q < 4; q++) {
            int e = e0 + q;
            if (e < E) d[q] = is64 ? (int)p64[(size_t)E + e] : p32[E + e];
            else d[q] = -1;
        }
#pragma unroll
        for (int q = 0; q < 4; q++)
            if (d[q] >= 0) atomicAdd(&off[d[q]], 1);
    }
    grid_bar(2 * G);

    // ---- phase 2a: block scan (blocks b < nscan, 1024 elems each), publish sums ----
    const int nscan = (N + CSR_T - 1) / CSR_T;
    int vdeg = 0, excl = 0;
    const int si = b * CSR_T + tid;
    if (b < nscan) {
        vdeg = (si < N) ? ldcg_i(&off[si]) : 0;
        int ts = vdeg;
#pragma unroll
        for (int o = 1; o < 32; o <<= 1) {
            int t = __shfl_up_sync(0xffffffffu, ts, o);
            if (lane >= o) ts += t;
        }
        if (lane == 31) swarp[wid] = ts;
        __syncthreads();
        if (wid == 0) {
            int w = swarp[lane];
#pragma unroll
            for (int o = 1; o < 32; o <<= 1) {
                int t = __shfl_up_sync(0xffffffffu, w, o);
                if (lane >= o) w += t;
            }
            swarp[lane] = w;
        }
        __syncthreads();
        int warp_base = (wid == 0) ? 0 : swarp[wid - 1];
        excl = warp_base + ts - vdeg;
        if (tid == 0) g_tile_sums[b] = swarp[31];
    }
    grid_bar(3 * G);

    // ---- phase 2b: add cross-block base, write exclusive prefix in place ----
    if (b < nscan) {
        if (wid == 0) {
            int acc = 0;
            for (int t = lane; t < b; t += 32)
                acc += atomicAdd(&g_tile_sums[t], 0);
#pragma unroll
            for (int o = 16; o; o >>= 1)
                acc += __shfl_xor_sync(0xffffffffu, acc, o);
            if (lane == 0) sbase = acc;
        }
        __syncthreads();
        if (si < N) off[si] = sbase + excl;
    }
    grid_bar(4 * G);

    // ---- phase 3: bucket fill. after: off[d] = END; begin(d) = off[d-1] (0 for d=0) ----
    for (int c = gid; c < nchunk; c += TT) {
        int e0 = c << 2;
        int s[4], d[4];
#pragma unroll
        for (int q = 0; q < 4; q++) {
            int e = e0 + q;
            if (e < E) {
                if (is64) { s[q] = (int)p64[e]; d[q] = (int)p64[(size_t)E + e]; }
                else      { s[q] = p32[e];      d[q] = p32[E + e]; }
            } else d[q] = -1;
        }
#pragma unroll
        for (int q = 0; q < 4; q++) {
            if (d[q] >= 0) {
                int pos = atomicAdd(&off[d[q]], 1);
                csrc[pos] = s[q];
            }
        }
    }

    // ---- final arrive (no wait): last block resets counter for next replay ----
    __threadfence();
    __syncthreads();
    if (tid == 0) {
        int old = atomicAdd(&g_bar, 1);
        if (old == 5 * G - 1) atomicExch(&g_bar, 0);
    }
}

// ---------------- gather1: 16 lanes/row, 8 halves/lane; 4-edge unrolled MLP ----------------
__global__ void __launch_bounds__(256) gather1_kernel(
    const __half* __restrict__ feat, const int* __restrict__ off,
    const int* __restrict__ csrc, __half* __restrict__ out, int N)
{
    int gid = blockIdx.x * 256 + threadIdx.x;
    int w = gid >> 4;
    int j = gid & 15;
    if (w >= N) return;
    int end = __ldg(&off[w]);
    int beg = (w == 0) ? 0 : __ldg(&off[w - 1]);

    float2 acc0 = make_float2(0.f, 0.f), acc1 = acc0, acc2 = acc0, acc3 = acc0;
    const __half* base = feat + j * 8;
    int k = beg;
    for (; k + 4 <= end; k += 4) {
        int s0 = __ldg(&csrc[k]);
        int s1 = __ldg(&csrc[k + 1]);
        int s2 = __ldg(&csrc[k + 2]);
        int s3 = __ldg(&csrc[k + 3]);
        uint4 r0 = *(const uint4*)(base + (size_t)s0 * D_IN);
        uint4 r1 = *(const uint4*)(base + (size_t)s1 * D_IN);
        uint4 r2 = *(const uint4*)(base + (size_t)s2 * D_IN);
        uint4 r3 = *(const uint4*)(base + (size_t)s3 * D_IN);
        float2 f;
        f = __half22float2(*(__half2*)&r0.x); acc0.x += f.x; acc0.y += f.y;
        f = __half22float2(*(__half2*)&r0.y); acc1.x += f.x; acc1.y += f.y;
        f = __half22float2(*(__half2*)&r0.z); acc2.x += f.x; acc2.y += f.y;
        f = __half22float2(*(__half2*)&r0.w); acc3.x += f.x; acc3.y += f.y;
        f = __half22float2(*(__half2*)&r1.x); acc0.x += f.x; acc0.y += f.y;
        f = __half22float2(*(__half2*)&r1.y); acc1.x += f.x; acc1.y += f.y;
        f = __half22float2(*(__half2*)&r1.z); acc2.x += f.x; acc2.y += f.y;
        f = __half22float2(*(__half2*)&r1.w); acc3.x += f.x; acc3.y += f.y;
        f = __half22float2(*(__half2*)&r2.x); acc0.x += f.x; acc0.y += f.y;
        f = __half22float2(*(__half2*)&r2.y); acc1.x += f.x; acc1.y += f.y;
        f = __half22float2(*(__half2*)&r2.z); acc2.x += f.x; acc2.y += f.y;
        f = __half22float2(*(__half2*)&r2.w); acc3.x += f.x; acc3.y += f.y;
        f = __half22float2(*(__half2*)&r3.x); acc0.x += f.x; acc0.y += f.y;
        f = __half22float2(*(__half2*)&r3.y); acc1.x += f.x; acc1.y += f.y;
        f = __half22float2(*(__half2*)&r3.z); acc2.x += f.x; acc2.y += f.y;
        f = __half22float2(*(__half2*)&r3.w); acc3.x += f.x; acc3.y += f.y;
    }
    for (; k < end; k++) {
        int s0 = __ldg(&csrc[k]);
        uint4 r0 = *(const uint4*)(base + (size_t)s0 * D_IN);
        float2 f;
        f = __half22float2(*(__half2*)&r0.x); acc0.x += f.x; acc0.y += f.y;
        f = __half22float2(*(__half2*)&r0.y); acc1.x += f.x; acc1.y += f.y;
        f = __half22float2(*(__half2*)&r0.z); acc2.x += f.x; acc2.y += f.y;
        f = __half22float2(*(__half2*)&r0.w); acc3.x += f.x; acc3.y += f.y;
    }
    uint4 o;
    *(__half2*)&o.x = __float22half2_rn(acc0);
    *(__half2*)&o.y = __float22half2_rn(acc1);
    *(__half2*)&o.z = __float22half2_rn(acc2);
    *(__half2*)&o.w = __float22half2_rn(acc3);
    *(uint4*)(out + (size_t)w * D_HID + j * 8) = o;
}

// ---------------- gemm1: h1h = [agg1h | x16] @ w1hT' + b (fp16 out); fused BN1 stats ----------------
__global__ void __launch_bounds__(256) gemm1_kernel(
    const __half* __restrict__ Ah, const __half* __restrict__ Axh,
    const __half* __restrict__ w1hT,
    const float* __restrict__ bias, __half* __restrict__ C, int M,
    double* __restrict__ sumd, double* __restrict__ sqd)
{
    constexpr int BM = 128, BN = 128, WN = 64, NT = 8;
    constexpr int KPAD = 8;
    __shared__ __half As[BM][32 + KPAD];
    __shared__ __half BsT[BN][32 + KPAD];
    __shared__ float shs[BN], shq[BN];

    const int tid = threadIdx.x;
    const int lane = tid & 31;
    const int wid = tid >> 5;
    const int warp_m = wid & 3;
    const int warp_n = wid >> 2;
    const int m0 = blockIdx.x * BM;
    const int tg = lane & 3;
    const int gi = lane >> 2;

    if (tid < BN) { shs[tid] = 0.f; shq[tid] = 0.f; }

    const int rA0 = tid >> 2,            cA0 = (tid & 3) << 3;
    const int rA1 = (tid + 256) >> 2,    cA1 = ((tid + 256) & 3) << 3;

    float acc[2][NT][4];
#pragma unroll
    for (int mt = 0; mt < 2; mt++)
#pragma unroll
        for (int nt = 0; nt < NT; nt++)
#pragma unroll
            for (int r = 0; r < 4; r++) acc[mt][nt][r] = 0.f;

    auto loadStage = [&](int it, uint4& a0, uint4& a1, uint4& b0, uint4& b1) {
        const __half* Asrc = (it < 4) ? Ah : Axh;
        int kloc = (it & 3) * 32;
        int kglob = it * 32;
        a0 = make_uint4(0, 0, 0, 0);
        a1 = make_uint4(0, 0, 0, 0);
        if (m0 + rA0 < M) a0 = *(const uint4*)(Asrc + (size_t)(m0 + rA0) * 128 + kloc + cA0);
        if (m0 + rA1 < M) a1 = *(const uint4*)(Asrc + (size_t)(m0 + rA1) * 128 + kloc + cA1);
        b0 = *(const uint4*)(w1hT + (size_t)rA0 * 256 + kglob + cA0);
        b1 = *(const uint4*)(w1hT + (size_t)rA1 * 256 + kglob + cA1);
    };

    uint4 a0, a1, b0, b1;
    loadStage(0, a0, a1, b0, b1);

    for (int it = 0; it < 8; it++) {
        *(uint4*)&As[rA0][cA0] = a0;
        *(uint4*)&As[rA1][cA1] = a1;
        *(uint4*)&BsT[rA0][cA0] = b0;
        *(uint4*)&BsT[rA1][cA1] = b1;
        __syncthreads();
        uint4 na0, na1, nb0, nb1;
        if (it < 7) loadStage(it + 1, na0, na1, nb0, nb1);

#pragma unroll
        for (int ks = 0; ks < 2; ks++) {
            int k16 = ks * 16;
            unsigned a[2][4];
#pragma unroll
            for (int mt = 0; mt < 2; mt++) {
                int rb = warp_m * 32 + mt * 16;
                a[mt][0] = *(const unsigned*)&As[rb + gi][k16 + 2 * tg];
                a[mt][1] = *(const unsigned*)&As[rb + 8 + gi][k16 + 2 * tg];
                a[mt][2] = *(const unsigned*)&As[rb + gi][k16 + 8 + 2 * tg];
                a[mt][3] = *(const unsigned*)&As[rb + 8 + gi][k16 + 8 + 2 * tg];
            }
            unsigned b[NT][2];
#pragma unroll
            for (int nt = 0; nt < NT; nt++) {
                int col = warp_n * WN + nt * 8 + gi;
                b[nt][0] = *(const unsigned*)&BsT[col][k16 + 2 * tg];
                b[nt][1] = *(const unsigned*)&BsT[col][k16 + 8 + 2 * tg];
            }
#pragma unroll
            for (int mt = 0; mt < 2; mt++)
#pragma unroll
                for (int nt = 0; nt < NT; nt++)
                    mma_f16(acc[mt][nt], a[mt], b[nt]);
        }
        __syncthreads();
        if (it < 7) { a0 = na0; a1 = na1; b0 = nb0; b1 = nb1; }
    }

#pragma unroll
    for (int nt = 0; nt < NT; nt++) {
        int col = warp_n * WN + nt * 8 + tg * 2;
        float bx = __ldg(&bias[col]);
        float by = __ldg(&bias[col + 1]);
        float s0 = 0.f, s1 = 0.f, q0 = 0.f, q1 = 0.f;
#pragma unroll
        for (int mt = 0; mt < 2; mt++) {
            int r0 = m0 + warp_m * 32 + mt * 16 + gi;
            int r1 = r0 + 8;
            float vx = acc[mt][nt][0] + bx, vy = acc[mt][nt][1] + by;
            float wx = acc[mt][nt][2] + bx, wy = acc[mt][nt][3] + by;
            if (r0 < M) {
                *(__half2*)(C + (size_t)r0 * BN + col) = __floats2half2_rn(vx, vy);
                s0 += vx; q0 += vx * vx; s1 += vy; q1 += vy * vy;
            }
            if (r1 < M) {
                *(__half2*)(C + (size_t)r1 * BN + col) = __floats2half2_rn(wx, wy);
                s0 += wx; q0 += wx * wx; s1 += wy; q1 += wy * wy;
            }
        }
#pragma unroll
        for (int msk = 4; msk < 32; msk <<= 1) {
            s0 += __shfl_xor_sync(0xffffffffu, s0, msk);
            s1 += __shfl_xor_sync(0xffffffffu, s1, msk);
            q0 += __shfl_xor_sync(0xffffffffu, q0, msk);
            q1 += __shfl_xor_sync(0xffffffffu, q1, msk);
        }
        if (gi == 0) {
            atomicAdd(&shs[col], s0);
            atomicAdd(&shs[col + 1], s1);
            atomicAdd(&shq[col], q0);
            atomicAdd(&shq[col + 1], q1);
        }
    }
    __syncthreads();
    if (tid < BN) {
        atomicAdd(&sumd[tid], (double)shs[tid]);
        atomicAdd(&sqd[tid], (double)shq[tid]);
    }
}

// ---------------- gemm2: [t16 | r2h] = relu(bn(h1h)) @ w2hT'; BN coeffs in-block ----------------
__global__ void __launch_bounds__(256) gemm2_kernel(
    const __half* __restrict__ A, const __half* __restrict__ w2hT,
    __half* __restrict__ r2h, __half* __restrict__ t16, int M,
    const double* __restrict__ stats, const float* __restrict__ gamma,
    const float* __restrict__ beta, float invM)
{
    constexpr int BM = 128, BK = 32, BN = 64, WN = 32, NT = 4;
    constexpr int KPAD = 8;
    __shared__ __half As[BM][BK + KPAD];
    __shared__ __half BsT[BN][BK + KPAD];
    __shared__ float sscale[128], sshift[128];

    const int tid = threadIdx.x;
    const int lane = tid & 31;
    const int wid = tid >> 5;
    const int warp_m = wid & 3;
    const int warp_n = wid >> 2;
    const int m0 = blockIdx.x * BM;
    const int tg = lane & 3;
    const int gi = lane >> 2;

    if (tid < 128) {
        double mu = stats[tid] * (double)invM;
        double var = stats[128 + tid] * (double)invM - mu * mu;
        float s = gamma[tid] * rsqrtf((float)var + 1e-5f);
        sscale[tid] = s;
        sshift[tid] = beta[tid] - (float)mu * s;
    }
    __syncthreads();

    float acc[2][NT][4];
#pragma unroll
    for (int mt = 0; mt < 2; mt++)
#pragma unroll
        for (int nt = 0; nt < NT; nt++)
#pragma unroll
            for (int r = 0; r < 4; r++) acc[mt][nt][r] = 0.f;

    for (int kc = 0; kc < D_HID; kc += BK) {
#pragma unroll
        for (int t = 0; t < 2; t++) {
            int v = tid + t * 256;
            int row = v >> 2;
            int c8 = (v & 3) << 3;
            uint4 rw = make_uint4(0, 0, 0, 0);
            if (m0 + row < M)
                rw = *(const uint4*)(A + (size_t)(m0 + row) * D_HID + kc + c8);
            int kg = kc + c8;
            uint4 outw;
            const unsigned* pin = (const unsigned*)&rw;
            unsigned* pout = (unsigned*)&outw;
#pragma unroll
            for (int q = 0; q < 4; q++) {
                float2 f = __half22float2(*(const __half2*)&pin[q]);
                int k0 = kg + q * 2;
                f.x = fmaxf(fmaf(f.x, sscale[k0], sshift[k0]), 0.f);
                f.y = fmaxf(fmaf(f.y, sscale[k0 + 1], sshift[k0 + 1]), 0.f);
                *(__half2*)&pout[q] = __float22half2_rn(f);
            }
            *(uint4*)&As[row][c8] = outw;
        }
        {
            int n = tid >> 2;
            int c8 = (tid & 3) << 3;
            uint4 rw = *(const uint4*)(w2hT + (size_t)n * 128 + kc + c8);
            *(uint4*)&BsT[n][c8] = rw;
        }
        __syncthreads();

#pragma unroll
        for (int ks = 0; ks < 2; ks++) {
            int k16 = ks * 16;
            unsigned a[2][4];
#pragma unroll
            for (int mt = 0; mt < 2; mt++) {
                int rb = warp_m * 32 + mt * 16;
                a[mt][0] = *(const unsigned*)&As[rb + gi][k16 + 2 * tg];
                a[mt][1] = *(const unsigned*)&As[rb + 8 + gi][k16 + 2 * tg];
                a[mt][2] = *(const unsigned*)&As[rb + gi][k16 + 8 + 2 * tg];
                a[mt][3] = *(const unsigned*)&As[rb + 8 + gi][k16 + 8 + 2 * tg];
            }
            unsigned b[NT][2];
#pragma unroll
            for (int nt = 0; nt < NT; nt++) {
                int col = warp_n * WN + nt * 8 + gi;
                b[nt][0] = *(const unsigned*)&BsT[col][k16 + 2 * tg];
                b[nt][1] = *(const unsigned*)&BsT[col][k16 + 8 + 2 * tg];
            }
#pragma unroll
            for (int mt = 0; mt < 2; mt++)
#pragma unroll
                for (int nt = 0; nt < NT; nt++)
                    mma_f16(acc[mt][nt], a[mt], b[nt]);
        }
        __syncthreads();
    }

#pragma unroll
    for (int mt = 0; mt < 2; mt++) {
        int r0 = m0 + warp_m * 32 + mt * 16 + gi;
        int r1 = r0 + 8;
#pragma unroll
        for (int nt = 0; nt < NT; nt++) {
            int col = warp_n * WN + nt * 8 + tg * 2;
            __half* dst = (warp_n == 0) ? t16 : r2h;
            int c = (warp_n == 0) ? col : (col - 32);
            if (r0 < M)
                *(__half2*)(dst + (size_t)r0 * 32 + c) =
                    __floats2half2_rn(acc[mt][nt][0], acc[mt][nt][1]);
            if (r1 < M)
                *(__half2*)(dst + (size_t)r1 * 32 + c) =
                    __floats2half2_rn(acc[mt][nt][2], acc[mt][nt][3]);
        }
    }
}

// ---------------- gather2 fused: agg2 = gather(t16) + r2h + bias; BN2 stats ----------------
__global__ void __launch_bounds__(256) gather2_fused_kernel(
    const __half* __restrict__ feat, const int* __restrict__ off,
    const int* __restrict__ csrc, const __half* __restrict__ r2h,
    const float* __restrict__ bias, float* __restrict__ out, int N,
    double* __restrict__ sumd, double* __restrict__ sqd)
{
    __shared__ float shs[32], shq[32];
    int tid = threadIdx.x;
    if (tid < 32) { shs[tid] = 0.f; shq[tid] = 0.f; }
    __syncthreads();

    int gid = blockIdx.x * 256 + tid;
    int w = gid >> 2;
    int j = gid & 3;
    bool valid = (w < N);

    float v[8];
#pragma unroll
    for (int q = 0; q < 8; q++) v[q] = 0.f;

    if (valid) {
        int end = __ldg(&off[w]);
        int beg = (w == 0) ? 0 : __ldg(&off[w - 1]);
        const __half* base = feat + j * 8;
        int k = beg;
        for (; k + 2 <= end; k += 2) {
            int s0 = __ldg(&csrc[k]);
            int s1 = __ldg(&csrc[k + 1]);
            uint4 r0 = *(const uint4*)(base + (size_t)s0 * 32);
            uint4 r1 = *(const uint4*)(base + (size_t)s1 * 32);
            float2 f;
            f = __half22float2(*(__half2*)&r0.x); v[0] += f.x; v[1] += f.y;
            f = __half22float2(*(__half2*)&r0.y); v[2] += f.x; v[3] += f.y;
            f = __half22float2(*(__half2*)&r0.z); v[4] += f.x; v[5] += f.y;
            f = __half22float2(*(__half2*)&r0.w); v[6] += f.x; v[7] += f.y;
            f = __half22float2(*(__half2*)&r1.x); v[0] += f.x; v[1] += f.y;
            f = __half22float2(*(__half2*)&r1.y); v[2] += f.x; v[3] += f.y;
            f = __half22float2(*(__half2*)&r1.z); v[4] += f.x; v[5] += f.y;
            f = __half22float2(*(__half2*)&r1.w); v[6] += f.x; v[7] += f.y;
        }
        if (k < end) {
            int s0 = __ldg(&csrc[k]);
            uint4 r0 = *(const uint4*)(base + (size_t)s0 * 32);
            float2 f;
            f = __half22float2(*(__half2*)&r0.x); v[0] += f.x; v[1] += f.y;
            f = __half22float2(*(__half2*)&r0.y); v[2] += f.x; v[3] += f.y;
            f = __half22float2(*(__half2*)&r0.z); v[4] += f.x; v[5] += f.y;
            f = __half22float2(*(__half2*)&r0.w); v[6] += f.x; v[7] += f.y;
        }
        uint4 rr = *(const uint4*)(r2h + (size_t)w * 32 + j * 8);
        const float* bp = bias + j * 8;
        const unsigned* pr = (const unsigned*)&rr;
#pragma unroll
        for (int q = 0; q < 4; q++) {
            float2 f = __half22float2(*(const __half2*)&pr[q]);
            v[q * 2 + 0] += f.x + __ldg(bp + q * 2 + 0);
            v[q * 2 + 1] += f.y + __ldg(bp + q * 2 + 1);
        }
        float* op = out + (size_t)w * D_OUT + j * 8;
        *(float4*)(op + 0) = make_float4(v[0], v[1], v[2], v[3]);
        *(float4*)(op + 4) = make_float4(v[4], v[5], v[6], v[7]);
    }

    float s[8], q[8];
#pragma unroll
    for (int t = 0; t < 8; t++) {
        s[t] = valid ? v[t] : 0.f;
        q[t] = valid ? v[t] * v[t] : 0.f;
    }
#pragma unroll
    for (int msk = 4; msk < 32; msk <<= 1)
#pragma unroll
        for (int t = 0; t < 8; t++) {
            s[t] += __shfl_xor_sync(0xffffffffu, s[t], msk);
            q[t] += __shfl_xor_sync(0xffffffffu, q[t], msk);
        }
    if ((tid & 31) < 4) {
#pragma unroll
        for (int t = 0; t < 8; t++) {
            atomicAdd(&shs[j * 8 + t], s[t]);
            atomicAdd(&shq[j * 8 + t], q[t]);
        }
    }
    __syncthreads();
    if (tid < 32) {
        atomicAdd(&sumd[tid], (double)shs[tid]);
        atomicAdd(&sqd[tid], (double)shq[tid]);
    }
}

// ---------------- final normalize/relu with in-block BN2 coefficients ----------------
__global__ void __launch_bounds__(256) bn_relu4_kernel(
    const float4* __restrict__ in, float4* __restrict__ out, long long n4,
    const double* __restrict__ stats, const float* __restrict__ gamma,
    const float* __restrict__ beta, float invM)
{
    __shared__ float sscale[32], sshift[32];
    if (threadIdx.x < 32) {
        int c = threadIdx.x;
        double mu = stats[c] * (double)invM;
        double var = stats[32 + c] * (double)invM - mu * mu;
        float s = gamma[c] * rsqrtf((float)var + 1e-5f);
        sscale[c] = s;
        sshift[c] = beta[c] - (float)mu * s;
    }
    __syncthreads();
    long long i = (long long)blockIdx.x * blockDim.x + threadIdx.x;
    long long stride = (long long)gridDim.x * blockDim.x;
    for (; i < n4; i += stride) {
        int c = (int)((i << 2) & 31);
        float4 v = in[i];
        v.x = fmaxf(fmaf(v.x, sscale[c + 0], sshift[c + 0]), 0.f);
        v.y = fmaxf(fmaf(v.y, sscale[c + 1], sshift[c + 1]), 0.f);
        v.z = fmaxf(fmaf(v.z, sscale[c + 2], sshift[c + 2]), 0.f);
        v.w = fmaxf(fmaf(v.w, sscale[c + 3], sshift[c + 3]), 0.f);
        out[i] = v;
    }
}

static inline int ceil_div_i(int a, int b) { return (a + b - 1) / b; }

// ---------------- launch ----------------
extern "C" void kernel_launch(void* const* d_in, const int* in_sizes, int n_in,
                              void* d_out, int out_size)
{
    const float* x      = (const float*)d_in[0];
    const void*  ei     = d_in[1];
    const float* Wrel1  = (const float*)d_in[2];
    const float* brel1  = (const float*)d_in[3];
    const float* Wroot1 = (const float*)d_in[4];
    const float* gamma1 = (const float*)d_in[5];
    const float* beta1  = (const float*)d_in[6];
    const float* Wrel2  = (const float*)d_in[7];
    const float* brel2  = (const float*)d_in[8];
    const float* Wroot2 = (const float*)d_in[9];
    const float* gamma2 = (const float*)d_in[10];
    const float* beta2  = (const float*)d_in[11];

    const int N = in_sizes[0] / D_IN;
    const int E = in_sizes[1] / 2;

    float *agg2;
    __half *x16, *agg1h, *h1h, *r2h, *t16, *w1hT, *w2hT;
    double* stats;
    int *off, *csrc;
    cudaGetSymbolAddress((void**)&x16, g_x16);
    cudaGetSymbolAddress((void**)&agg1h, g_agg1h);
    cudaGetSymbolAddress((void**)&h1h, g_h1h);
    cudaGetSymbolAddress((void**)&r2h, g_r2h);
    cudaGetSymbolAddress((void**)&t16, g_t16);
    cudaGetSymbolAddress((void**)&agg2, g_agg2);
    cudaGetSymbolAddress((void**)&stats, g_stats);
    cudaGetSymbolAddress((void**)&w1hT, g_w1hT);
    cudaGetSymbolAddress((void**)&w2hT, g_w2hT);
    cudaGetSymbolAddress((void**)&off, g_off);
    cudaGetSymbolAddress((void**)&csrc, g_csrc);

    const float invM = 1.0f / (float)N;

    static cudaStream_t s2 = nullptr;
    static cudaEvent_t evStart = nullptr, evJoin = nullptr;
    if (!s2) {
        cudaStreamCreateWithFlags(&s2, cudaStreamNonBlocking);
        cudaEventCreateWithFlags(&evStart, cudaEventDisableTiming);
        cudaEventCreateWithFlags(&evJoin, cudaEventDisableTiming);
    }

    // ---- fork: persistent CSR build on main, data-prep on s2 ----
    cudaEventRecord(evStart, 0);
    cudaStreamWaitEvent(s2, evStart, 0);

    init_kernel<<<1024, 256, 0, s2>>>(stats, x, x16, (long long)N * D_IN / 2,
                                      Wrel1, Wroot1, Wrel2, Wroot2, w1hT, w2hT);
    cudaEventRecord(evJoin, s2);

    csr_build_kernel<<<CSR_G, CSR_T>>>(ei, E, off, csrc, N);

    // ---- join ----
    cudaStreamWaitEvent(0, evJoin, 0);
    gather1_kernel<<<ceil_div_i(N * 16, 256), 256>>>(x16, off, csrc, agg1h, N);
    gemm1_kernel<<<ceil_div_i(N, 128), 256>>>(
        agg1h, x16, w1hT, brel1, h1h, N, stats, stats + 128);

    gemm2_kernel<<<ceil_div_i(N, 128), 256>>>(h1h, w2hT, r2h, t16, N,
                                              stats, gamma1, beta1, invM);
    gather2_fused_kernel<<<ceil_div_i(N * 4, 256), 256>>>(
        t16, off, csrc, r2h, brel2, agg2, N, stats + 256, stats + 288);

    bn_relu4_kernel<<<1024, 256>>>((const float4*)agg2, (float4*)d_out,
                                   (long long)N * D_OUT / 4,
                                   stats + 256, gamma2, beta2, invM);
}

// round 16
// speedup vs baseline: 1.1053x; 1.1053x over previous
#include <cuda_runtime.h>
#include <cuda_fp16.h>
#include <cstddef>

#define D_IN  128
#define D_HID 128
#define D_OUT 32
#define NMAX  100000
#define EMAX  1601000
#define SC_T  256
#define SC_I  8
#define SC_TILE (SC_T * SC_I)
#define NCHUNKMAX 128

// ---------------- static device scratch (no runtime allocation) ----------------
__device__ __half g_x16 [(size_t)NMAX * D_IN];
__device__ __half g_agg1h[(size_t)NMAX * D_HID];
__device__ __half g_h1h [(size_t)NMAX * D_HID];   // pre-BN h1 (fp16)
__device__ __half g_r2h [(size_t)NMAX * 32];
__device__ __half g_t16 [(size_t)NMAX * 32];
__device__ float  g_agg2[(size_t)NMAX * D_OUT];
__device__ double g_stats[320];
__device__ __half g_w1hT [128 * 256];             // [n][k]: k<128 Wrel1, k>=128 Wroot1
__device__ __half g_w2hT [64 * 128];
__device__ int    g_off[NMAX + 8];
__device__ int    g_tile_sums[NCHUNKMAX];
__device__ int    g_pub_count;
__device__ int    g_csrc[EMAX];
__device__ int    g_is64;

// ---------------- fp16 MMA + cp.async helpers ----------------
__device__ __forceinline__ void mma_f16(float c[4], const unsigned a[4], const unsigned b[2]) {
    asm volatile(
        "mma.sync.aligned.m16n8k16.row.col.f32.f16.f16.f32 "
        "{%0,%1,%2,%3}, {%4,%5,%6,%7}, {%8,%9}, {%0,%1,%2,%3};"
        : "+f"(c[0]), "+f"(c[1]), "+f"(c[2]), "+f"(c[3])
        : "r"(a[0]), "r"(a[1]), "r"(a[2]), "r"(a[3]), "r"(b[0]), "r"(b[1]));
}
__device__ __forceinline__ void cp_async16(unsigned saddr, const void* g, int srcBytes) {
    asm volatile("cp.async.cg.shared.global [%0], [%1], 16, %2;"
                 :: "r"(saddr), "l"(g), "r"(srcBytes));
}
__device__ __forceinline__ void cp_commit() {
    asm volatile("cp.async.commit_group;");
}
template <int NN>
__device__ __forceinline__ void cp_wait() {
    asm volatile("cp.async.wait_group %0;" :: "n"(NN));
}

// ---------------- main chain: zero off + pub state, detect dtype ----------------
__global__ void __launch_bounds__(256) zero_off_kernel(const int* ei, int E, int* off, int N) {
    int i = blockIdx.x * 256 + threadIdx.x;
    int stride = gridDim.x * 256;
    for (int t = i; t <= N; t += stride) off[t] = 0;
    for (int t = i; t < NCHUNKMAX; t += stride) g_tile_sums[t] = 0;
    if (blockIdx.x == 0 && threadIdx.x == 0) {
        g_pub_count = 0;
        int n = 2 * E;
        int allzero = 1;
        for (int k = 1; k < 256 && k < n; k += 2) {
            if (ei[k] != 0) { allzero = 0; break; }
        }
        g_is64 = allzero;
    }
}

// ---------------- side chain: stats zero + x->fp16 + weight prep ----------------
__global__ void __launch_bounds__(256) init_kernel(
    double* stats,
    const float* __restrict__ x, __half* __restrict__ x16, long long nh2,
    const float* __restrict__ Wrel1, const float* __restrict__ Wroot1,
    const float* __restrict__ Wrel2, const float* __restrict__ Wroot2,
    __half* __restrict__ w1hT, __half* __restrict__ w2hT)
{
    long long i = (long long)blockIdx.x * 256 + threadIdx.x;
    long long stride = (long long)gridDim.x * 256;
    for (long long t = i; t < 320; t += stride) stats[t] = 0.0;
    const float2* xf2 = (const float2*)x;
    __half2* xh2 = (__half2*)x16;
    for (long long t = i; t < nh2; t += stride)
        xh2[t] = __float22half2_rn(xf2[t]);
    for (long long t = i; t < 128 * 256; t += stride) {
        int n = (int)(t >> 8), k = (int)(t & 255);
        float v = (k < 128) ? Wrel1[k * 128 + n] : Wroot1[(k - 128) * 128 + n];
        w1hT[t] = __float2half_rn(v);
    }
    for (long long t = i; t < 64 * 128; t += stride) {
        int n = (int)(t >> 7), k = (int)(t & 127);
        float v = (n < 32) ? Wrel2[k * 32 + n] : Wroot2[k * 32 + (n - 32)];
        w2hT[t] = __float2half_rn(v);
    }
}

__device__ __forceinline__ void load_edge(const void* eiv, int E, int e, int& s, int& d) {
    if (g_is64) {
        const long long* p = (const long long*)eiv;
        s = (int)p[e];
        d = (int)p[(size_t)E + e];
    } else {
        const int* p = (const int*)eiv;
        s = p[e];
        d = p[E + e];
    }
}

// ---------------- CSR build ----------------
__global__ void __launch_bounds__(256) hist_kernel(const void* eiv, int E, int* deg) {
    int base = (blockIdx.x * 256 + threadIdx.x) * 8;
    const int is64 = g_is64;
    int d[8];
#pragma unroll
    for (int q = 0; q < 8; q++) {
        int e = base + q;
        if (e < E) {
            if (is64) d[q] = (int)((const long long*)eiv)[(size_t)E + e];
            else      d[q] = ((const int*)eiv)[E + e];
        } else d[q] = -1;
    }
#pragma unroll
    for (int q = 0; q < 8; q++)
        if (d[q] >= 0) atomicAdd(&deg[d[q]], 1);
}

__global__ void __launch_bounds__(SC_T) scan_pub_kernel(int* off, int N) {
    __shared__ int swarp[8];
    __shared__ int base_sh;
    const int b = blockIdx.x;
    const int tid = threadIdx.x;
    const int lane = tid & 31, wid = tid >> 5;
    const int i0 = b * SC_TILE + tid * SC_I;

    int v[SC_I];
    {
        int4 p0 = *(const int4*)(off + i0);
        int4 p1 = *(const int4*)(off + i0 + 4);
        v[0] = p0.x; v[1] = p0.y; v[2] = p0.z; v[3] = p0.w;
        v[4] = p1.x; v[5] = p1.y; v[6] = p1.z; v[7] = p1.w;
#pragma unroll
        for (int k = 0; k < SC_I; k++)
            if (i0 + k >= N) v[k] = 0;
    }
#pragma unroll
    for (int k = 1; k < SC_I; k++) v[k] += v[k - 1];
    int tsum = v[SC_I - 1];

    int ts = tsum;
#pragma unroll
    for (int o = 1; o < 32; o <<= 1) {
        int t = __shfl_up_sync(0xffffffffu, ts, o);
        if (lane >= o) ts += t;
    }
    if (lane == 31) swarp[wid] = ts;
    __syncthreads();
    if (wid == 0) {
        int w = (lane < 8) ? swarp[lane] : 0;
#pragma unroll
        for (int o = 1; o < 8; o <<= 1) {
            int t = __shfl_up_sync(0xffffffffu, w, o);
            if (lane >= o) w += t;
        }
        if (lane < 8) swarp[lane] = w;
    }
    __syncthreads();
    const int block_total = swarp[7];
    const int warp_base = (wid == 0) ? 0 : swarp[wid - 1];
    const int texcl = warp_base + ts - tsum;

    if (tid == 0) {
        g_tile_sums[b] = block_total;
        __threadfence();
        atomicAdd(&g_pub_count, 1);
    }
    if (wid == 0) {
        if (lane == 0) {
            while (atomicAdd(&g_pub_count, 0) < (int)gridDim.x) {}
        }
        __syncwarp();
        int acc = 0;
        for (int t = lane; t < b; t += 32)
            acc += atomicAdd(&g_tile_sums[t], 0);
#pragma unroll
        for (int o = 16; o; o >>= 1)
            acc += __shfl_xor_sync(0xffffffffu, acc, o);
        if (lane == 0) base_sh = acc;
    }
    __syncthreads();
    const int base = base_sh + texcl;
#pragma unroll
    for (int k = 0; k < SC_I; k++) {
        int idx = i0 + k;
        if (idx < N) off[idx] = base + ((k == 0) ? 0 : v[k - 1]);
    }
}

__global__ void __launch_bounds__(256) fill_kernel(const void* eiv, int E, int* off, int* csrc) {
    int base = (blockIdx.x * 256 + threadIdx.x) * 4;
    int s[4], d[4];
#pragma unroll
    for (int q = 0; q < 4; q++) {
        int e = base + q;
        if (e < E) load_edge(eiv, E, e, s[q], d[q]);
        else d[q] = -1;
    }
#pragma unroll
    for (int q = 0; q < 4; q++) {
        if (d[q] >= 0) {
            int pos = atomicAdd(&off[d[q]], 1);
            csrc[pos] = s[q];
        }
    }
}

// ---------------- gather1: 16 lanes/row, 8 halves/lane; 4-edge unrolled MLP ----------------
__global__ void __launch_bounds__(256) gather1_kernel(
    const __half* __restrict__ feat, const int* __restrict__ off,
    const int* __restrict__ csrc, __half* __restrict__ out, int N)
{
    int gid = blockIdx.x * 256 + threadIdx.x;
    int w = gid >> 4;
    int j = gid & 15;
    if (w >= N) return;
    int end = __ldg(&off[w]);
    int beg = (w == 0) ? 0 : __ldg(&off[w - 1]);

    float2 acc0 = make_float2(0.f, 0.f), acc1 = acc0, acc2 = acc0, acc3 = acc0;
    const __half* base = feat + j * 8;
    int k = beg;
    for (; k + 4 <= end; k += 4) {
        int s0 = __ldg(&csrc[k]);
        int s1 = __ldg(&csrc[k + 1]);
        int s2 = __ldg(&csrc[k + 2]);
        int s3 = __ldg(&csrc[k + 3]);
        uint4 r0 = *(const uint4*)(base + (size_t)s0 * D_IN);
        uint4 r1 = *(const uint4*)(base + (size_t)s1 * D_IN);
        uint4 r2 = *(const uint4*)(base + (size_t)s2 * D_IN);
        uint4 r3 = *(const uint4*)(base + (size_t)s3 * D_IN);
        float2 f;
        f = __half22float2(*(__half2*)&r0.x); acc0.x += f.x; acc0.y += f.y;
        f = __half22float2(*(__half2*)&r0.y); acc1.x += f.x; acc1.y += f.y;
        f = __half22float2(*(__half2*)&r0.z); acc2.x += f.x; acc2.y += f.y;
        f = __half22float2(*(__half2*)&r0.w); acc3.x += f.x; acc3.y += f.y;
        f = __half22float2(*(__half2*)&r1.x); acc0.x += f.x; acc0.y += f.y;
        f = __half22float2(*(__half2*)&r1.y); acc1.x += f.x; acc1.y += f.y;
        f = __half22float2(*(__half2*)&r1.z); acc2.x += f.x; acc2.y += f.y;
        f = __half22float2(*(__half2*)&r1.w); acc3.x += f.x; acc3.y += f.y;
        f = __half22float2(*(__half2*)&r2.x); acc0.x += f.x; acc0.y += f.y;
        f = __half22float2(*(__half2*)&r2.y); acc1.x += f.x; acc1.y += f.y;
        f = __half22float2(*(__half2*)&r2.z); acc2.x += f.x; acc2.y += f.y;
        f = __half22float2(*(__half2*)&r2.w); acc3.x += f.x; acc3.y += f.y;
        f = __half22float2(*(__half2*)&r3.x); acc0.x += f.x; acc0.y += f.y;
        f = __half22float2(*(__half2*)&r3.y); acc1.x += f.x; acc1.y += f.y;
        f = __half22float2(*(__half2*)&r3.z); acc2.x += f.x; acc2.y += f.y;
        f = __half22float2(*(__half2*)&r3.w); acc3.x += f.x; acc3.y += f.y;
    }
    for (; k < end; k++) {
        int s0 = __ldg(&csrc[k]);
        uint4 r0 = *(const uint4*)(base + (size_t)s0 * D_IN);
        float2 f;
        f = __half22float2(*(__half2*)&r0.x); acc0.x += f.x; acc0.y += f.y;
        f = __half22float2(*(__half2*)&r0.y); acc1.x += f.x; acc1.y += f.y;
        f = __half22float2(*(__half2*)&r0.z); acc2.x += f.x; acc2.y += f.y;
        f = __half22float2(*(__half2*)&r0.w); acc3.x += f.x; acc3.y += f.y;
    }
    uint4 o;
    *(__half2*)&o.x = __float22half2_rn(acc0);
    *(__half2*)&o.y = __float22half2_rn(acc1);
    *(__half2*)&o.z = __float22half2_rn(acc2);
    *(__half2*)&o.w = __float22half2_rn(acc3);
    *(uint4*)(out + (size_t)w * D_HID + j * 8) = o;
}

// ---------------- gemm1: cp.async double-buffered; h1h = [agg1h|x16] @ w1hT' + b; BN1 stats ----------------
__global__ void __launch_bounds__(256) gemm1_kernel(
    const __half* __restrict__ Ah, const __half* __restrict__ Axh,
    const __half* __restrict__ w1hT,
    const float* __restrict__ bias, __half* __restrict__ C, int M,
    double* __restrict__ sumd, double* __restrict__ sqd)
{
    constexpr int BM = 128, BN = 128, WN = 64, NT = 8;
    constexpr int KPAD = 8;
    constexpr int LDA = 32 + KPAD;
    __shared__ __half As[2][BM][LDA];
    __shared__ __half BsT[2][BN][LDA];
    __shared__ float shs[BN], shq[BN];

    const int tid = threadIdx.x;
    const int lane = tid & 31;
    const int wid = tid >> 5;
    const int warp_m = wid & 3;
    const int warp_n = wid >> 2;
    const int m0 = blockIdx.x * BM;
    const int tg = lane & 3;
    const int gi = lane >> 2;

    if (tid < BN) { shs[tid] = 0.f; shq[tid] = 0.f; }

    // staging coordinates: 512 uint4 per tile, 2 per thread
    const int rA0 = tid >> 2,            cA0 = (tid & 3) << 3;
    const int rA1 = (tid + 256) >> 2,    cA1 = ((tid + 256) & 3) << 3;
    const bool v0 = (m0 + rA0 < M), v1 = (m0 + rA1 < M);

    float acc[2][NT][4];
#pragma unroll
    for (int mt = 0; mt < 2; mt++)
#pragma unroll
        for (int nt = 0; nt < NT; nt++)
#pragma unroll
            for (int r = 0; r < 4; r++) acc[mt][nt][r] = 0.f;

    auto issueStage = [&](int it, int buf) {
        const __half* Asrc = (it < 4) ? Ah : Axh;
        int kloc = (it & 3) * 32;
        int kglob = it * 32;
        unsigned a0s = (unsigned)__cvta_generic_to_shared(&As[buf][rA0][cA0]);
        unsigned a1s = (unsigned)__cvta_generic_to_shared(&As[buf][rA1][cA1]);
        unsigned b0s = (unsigned)__cvta_generic_to_shared(&BsT[buf][rA0][cA0]);
        unsigned b1s = (unsigned)__cvta_generic_to_shared(&BsT[buf][rA1][cA1]);
        cp_async16(a0s, Asrc + (size_t)(m0 + rA0) * 128 + kloc + cA0, v0 ? 16 : 0);
        cp_async16(a1s, Asrc + (size_t)(m0 + rA1) * 128 + kloc + cA1, v1 ? 16 : 0);
        cp_async16(b0s, w1hT + (size_t)rA0 * 256 + kglob + cA0, 16);
        cp_async16(b1s, w1hT + (size_t)rA1 * 256 + kglob + cA1, 16);
        cp_commit();
    };

    issueStage(0, 0);

    for (int it = 0; it < 8; it++) {
        int buf = it & 1;
        if (it < 7) {
            issueStage(it + 1, buf ^ 1);
            cp_wait<1>();
        } else {
            cp_wait<0>();
        }
        __syncthreads();

#pragma unroll
        for (int ks = 0; ks < 2; ks++) {
            int k16 = ks * 16;
            unsigned a[2][4];
#pragma unroll
            for (int mt = 0; mt < 2; mt++) {
                int rb = warp_m * 32 + mt * 16;
                a[mt][0] = *(const unsigned*)&As[buf][rb + gi][k16 + 2 * tg];
                a[mt][1] = *(const unsigned*)&As[buf][rb + 8 + gi][k16 + 2 * tg];
                a[mt][2] = *(const unsigned*)&As[buf][rb + gi][k16 + 8 + 2 * tg];
                a[mt][3] = *(const unsigned*)&As[buf][rb + 8 + gi][k16 + 8 + 2 * tg];
            }
            unsigned b[NT][2];
#pragma unroll
            for (int nt = 0; nt < NT; nt++) {
                int col = warp_n * WN + nt * 8 + gi;
                b[nt][0] = *(const unsigned*)&BsT[buf][col][k16 + 2 * tg];
                b[nt][1] = *(const unsigned*)&BsT[buf][col][k16 + 8 + 2 * tg];
            }
#pragma unroll
            for (int mt = 0; mt < 2; mt++)
#pragma unroll
                for (int nt = 0; nt < NT; nt++)
                    mma_f16(acc[mt][nt], a[mt], b[nt]);
        }
        __syncthreads();
    }

#pragma unroll
    for (int nt = 0; nt < NT; nt++) {
        int col = warp_n * WN + nt * 8 + tg * 2;
        float bx = __ldg(&bias[col]);
        float by = __ldg(&bias[col + 1]);
        float s0 = 0.f, s1 = 0.f, q0 = 0.f, q1 = 0.f;
#pragma unroll
        for (int mt = 0; mt < 2; mt++) {
            int r0 = m0 + warp_m * 32 + mt * 16 + gi;
            int r1 = r0 + 8;
            float vx = acc[mt][nt][0] + bx, vy = acc[mt][nt][1] + by;
            float wx = acc[mt][nt][2] + bx, wy = acc[mt][nt][3] + by;
            if (r0 < M) {
                *(__half2*)(C + (size_t)r0 * BN + col) = __floats2half2_rn(vx, vy);
                s0 += vx; q0 += vx * vx; s1 += vy; q1 += vy * vy;
            }
            if (r1 < M) {
                *(__half2*)(C + (size_t)r1 * BN + col) = __floats2half2_rn(wx, wy);
                s0 += wx; q0 += wx * wx; s1 += wy; q1 += wy * wy;
            }
        }
#pragma unroll
        for (int msk = 4; msk < 32; msk <<= 1) {
            s0 += __shfl_xor_sync(0xffffffffu, s0, msk);
            s1 += __shfl_xor_sync(0xffffffffu, s1, msk);
            q0 += __shfl_xor_sync(0xffffffffu, q0, msk);
            q1 += __shfl_xor_sync(0xffffffffu, q1, msk);
        }
        if (gi == 0) {
            atomicAdd(&shs[col], s0);
            atomicAdd(&shs[col + 1], s1);
            atomicAdd(&shq[col], q0);
            atomicAdd(&shq[col + 1], q1);
        }
    }
    __syncthreads();
    if (tid < BN) {
        atomicAdd(&sumd[tid], (double)shs[tid]);
        atomicAdd(&sqd[tid], (double)shq[tid]);
    }
}

// ---------------- gemm2: [t16 | r2h] = relu(bn(h1h)) @ w2hT'; BN coeffs in-block ----------------
__global__ void __launch_bounds__(256) gemm2_kernel(
    const __half* __restrict__ A, const __half* __restrict__ w2hT,
    __half* __restrict__ r2h, __half* __restrict__ t16, int M,
    const double* __restrict__ stats, const float* __restrict__ gamma,
    const float* __restrict__ beta, float invM)
{
    constexpr int BM = 128, BK = 32, BN = 64, WN = 32, NT = 4;
    constexpr int KPAD = 8;
    __shared__ __half As[BM][BK + KPAD];
    __shared__ __half BsT[BN][BK + KPAD];
    __shared__ float sscale[128], sshift[128];

    const int tid = threadIdx.x;
    const int lane = tid & 31;
    const int wid = tid >> 5;
    const int warp_m = wid & 3;
    const int warp_n = wid >> 2;
    const int m0 = blockIdx.x * BM;
    const int tg = lane & 3;
    const int gi = lane >> 2;

    if (tid < 128) {
        double mu = stats[tid] * (double)invM;
        double var = stats[128 + tid] * (double)invM - mu * mu;
        float s = gamma[tid] * rsqrtf((float)var + 1e-5f);
        sscale[tid] = s;
        sshift[tid] = beta[tid] - (float)mu * s;
    }
    __syncthreads();

    float acc[2][NT][4];
#pragma unroll
    for (int mt = 0; mt < 2; mt++)
#pragma unroll
        for (int nt = 0; nt < NT; nt++)
#pragma unroll
            for (int r = 0; r < 4; r++) acc[mt][nt][r] = 0.f;

    for (int kc = 0; kc < D_HID; kc += BK) {
#pragma unroll
        for (int t = 0; t < 2; t++) {
            int v = tid + t * 256;
            int row = v >> 2;
            int c8 = (v & 3) << 3;
            uint4 rw = make_uint4(0, 0, 0, 0);
            if (m0 + row < M)
                rw = *(const uint4*)(A + (size_t)(m0 + row) * D_HID + kc + c8);
            int kg = kc + c8;
            uint4 outw;
            const unsigned* pin = (const unsigned*)&rw;
            unsigned* pout = (unsigned*)&outw;
#pragma unroll
            for (int q = 0; q < 4; q++) {
                float2 f = __half22float2(*(const __half2*)&pin[q]);
                int k0 = kg + q * 2;
                f.x = fmaxf(fmaf(f.x, sscale[k0], sshift[k0]), 0.f);
                f.y = fmaxf(fmaf(f.y, sscale[k0 + 1], sshift[k0 + 1]), 0.f);
                *(__half2*)&pout[q] = __float22half2_rn(f);
            }
            *(uint4*)&As[row][c8] = outw;
        }
        {
            int n = tid >> 2;
            int c8 = (tid & 3) << 3;
            uint4 rw = *(const uint4*)(w2hT + (size_t)n * 128 + kc + c8);
            *(uint4*)&BsT[n][c8] = rw;
        }
        __syncthreads();

#pragma unroll
        for (int ks = 0; ks < 2; ks++) {
            int k16 = ks * 16;
            unsigned a[2][4];
#pragma unroll
            for (int mt = 0; mt < 2; mt++) {
                int rb = warp_m * 32 + mt * 16;
                a[mt][0] = *(const unsigned*)&As[rb + gi][k16 + 2 * tg];
                a[mt][1] = *(const unsigned*)&As[rb + 8 + gi][k16 + 2 * tg];
                a[mt][2] = *(const unsigned*)&As[rb + gi][k16 + 8 + 2 * tg];
                a[mt][3] = *(const unsigned*)&As[rb + 8 + gi][k16 + 8 + 2 * tg];
            }
            unsigned b[NT][2];
#pragma unroll
            for (int nt = 0; nt < NT; nt++) {
                int col = warp_n * WN + nt * 8 + gi;
                b[nt][0] = *(const unsigned*)&BsT[col][k16 + 2 * tg];
                b[nt][1] = *(const unsigned*)&BsT[col][k16 + 8 + 2 * tg];
            }
#pragma unroll
            for (int mt = 0; mt < 2; mt++)
#pragma unroll
                for (int nt = 0; nt < NT; nt++)
                    mma_f16(acc[mt][nt], a[mt], b[nt]);
        }
        __syncthreads();
    }

#pragma unroll
    for (int mt = 0; mt < 2; mt++) {
        int r0 = m0 + warp_m * 32 + mt * 16 + gi;
        int r1 = r0 + 8;
#pragma unroll
        for (int nt = 0; nt < NT; nt++) {
            int col = warp_n * WN + nt * 8 + tg * 2;
            __half* dst = (warp_n == 0) ? t16 : r2h;
            int c = (warp_n == 0) ? col : (col - 32);
            if (r0 < M)
                *(__half2*)(dst + (size_t)r0 * 32 + c) =
                    __floats2half2_rn(acc[mt][nt][0], acc[mt][nt][1]);
            if (r1 < M)
                *(__half2*)(dst + (size_t)r1 * 32 + c) =
                    __floats2half2_rn(acc[mt][nt][2], acc[mt][nt][3]);
        }
    }
}

// ---------------- gather2 fused: agg2 = gather(t16) + r2h + bias; BN2 stats ----------------
__global__ void __launch_bounds__(256) gather2_fused_kernel(
    const __half* __restrict__ feat, const int* __restrict__ off,
    const int* __restrict__ csrc, const __half* __restrict__ r2h,
    const float* __restrict__ bias, float* __restrict__ out, int N,
    double* __restrict__ sumd, double* __restrict__ sqd)
{
    __shared__ float shs[32], shq[32];
    int tid = threadIdx.x;
    if (tid < 32) { shs[tid] = 0.f; shq[tid] = 0.f; }
    __syncthreads();

    int gid = blockIdx.x * 256 + tid;
    int w = gid >> 2;
    int j = gid & 3;
    bool valid = (w < N);

    float v[8];
#pragma unroll
    for (int q = 0; q < 8; q++) v[q] = 0.f;

    if (valid) {
        int end = __ldg(&off[w]);
        int beg = (w == 0) ? 0 : __ldg(&off[w - 1]);
        const __half* base = feat + j * 8;
        int k = beg;
        for (; k + 2 <= end; k += 2) {
            int s0 = __ldg(&csrc[k]);
            int s1 = __ldg(&csrc[k + 1]);
            uint4 r0 = *(const uint4*)(base + (size_t)s0 * 32);
            uint4 r1 = *(const uint4*)(base + (size_t)s1 * 32);
            float2 f;
            f = __half22float2(*(__half2*)&r0.x); v[0] += f.x; v[1] += f.y;
            f = __half22float2(*(__half2*)&r0.y); v[2] += f.x; v[3] += f.y;
            f = __half22float2(*(__half2*)&r0.z); v[4] += f.x; v[5] += f.y;
            f = __half22float2(*(__half2*)&r0.w); v[6] += f.x; v[7] += f.y;
            f = __half22float2(*(__half2*)&r1.x); v[0] += f.x; v[1] += f.y;
            f = __half22float2(*(__half2*)&r1.y); v[2] += f.x; v[3] += f.y;
            f = __half22float2(*(__half2*)&r1.z); v[4] += f.x; v[5] += f.y;
            f = __half22float2(*(__half2*)&r1.w); v[6] += f.x; v[7] += f.y;
        }
        if (k < end) {
            int s0 = __ldg(&csrc[k]);
            uint4 r0 = *(const uint4*)(base + (size_t)s0 * 32);
            float2 f;
            f = __half22float2(*(__half2*)&r0.x); v[0] += f.x; v[1] += f.y;
            f = __half22float2(*(__half2*)&r0.y); v[2] += f.x; v[3] += f.y;
            f = __half22float2(*(__half2*)&r0.z); v[4] += f.x; v[5] += f.y;
            f = __half22float2(*(__half2*)&r0.w); v[6] += f.x; v[7] += f.y;
        }
        uint4 rr = *(const uint4*)(r2h + (size_t)w * 32 + j * 8);
        const float* bp = bias + j * 8;
        const unsigned* pr = (const unsigned*)&rr;
#pragma unroll
        for (int q = 0; q < 4; q++) {
            float2 f = __half22float2(*(const __half2*)&pr[q]);
            v[q * 2 + 0] += f.x + __ldg(bp + q * 2 + 0);
            v[q * 2 + 1] += f.y + __ldg(bp + q * 2 + 1);
        }
        float* op = out + (size_t)w * D_OUT + j * 8;
        *(float4*)(op + 0) = make_float4(v[0], v[1], v[2], v[3]);
        *(float4*)(op + 4) = make_float4(v[4], v[5], v[6], v[7]);
    }

    float s[8], q[8];
#pragma unroll
    for (int t = 0; t < 8; t++) {
        s[t] = valid ? v[t] : 0.f;
        q[t] = valid ? v[t] * v[t] : 0.f;
    }
#pragma unroll
    for (int msk = 4; msk < 32; msk <<= 1)
#pragma unroll
        for (int t = 0; t < 8; t++) {
            s[t] += __shfl_xor_sync(0xffffffffu, s[t], msk);
            q[t] += __shfl_xor_sync(0xffffffffu, q[t], msk);
        }
    if ((tid & 31) < 4) {
#pragma unroll
        for (int t = 0; t < 8; t++) {
            atomicAdd(&shs[j * 8 + t], s[t]);
            atomicAdd(&shq[j * 8 + t], q[t]);
        }
    }
    __syncthreads();
    if (tid < 32) {
        atomicAdd(&sumd[tid], (double)shs[tid]);
        atomicAdd(&sqd[tid], (double)shq[tid]);
    }
}

// ---------------- final normalize/relu with in-block BN2 coefficients ----------------
__global__ void __launch_bounds__(256) bn_relu4_kernel(
    const float4* __restrict__ in, float4* __restrict__ out, long long n4,
    const double* __restrict__ stats, const float* __restrict__ gamma,
    const float* __restrict__ beta, float invM)
{
    __shared__ float sscale[32], sshift[32];
    if (threadIdx.x < 32) {
        int c = threadIdx.x;
        double mu = stats[c] * (double)invM;
        double var = stats[32 + c] * (double)invM - mu * mu;
        float s = gamma[c] * rsqrtf((float)var + 1e-5f);
        sscale[c] = s;
        sshift[c] = beta[c] - (float)mu * s;
    }
    __syncthreads();
    long long i = (long long)blockIdx.x * blockDim.x + threadIdx.x;
    long long stride = (long long)gridDim.x * blockDim.x;
    for (; i < n4; i += stride) {
        int c = (int)((i << 2) & 31);
        float4 v = in[i];
        v.x = fmaxf(fmaf(v.x, sscale[c + 0], sshift[c + 0]), 0.f);
        v.y = fmaxf(fmaf(v.y, sscale[c + 1], sshift[c + 1]), 0.f);
        v.z = fmaxf(fmaf(v.z, sscale[c + 2], sshift[c + 2]), 0.f);
        v.w = fmaxf(fmaf(v.w, sscale[c + 3], sshift[c + 3]), 0.f);
        out[i] = v;
    }
}

static inline int ceil_div_i(int a, int b) { return (a + b - 1) / b; }

// ---------------- launch ----------------
extern "C" void kernel_launch(void* const* d_in, const int* in_sizes, int n_in,
                              void* d_out, int out_size)
{
    const float* x      = (const float*)d_in[0];
    const void*  ei     = d_in[1];
    const float* Wrel1  = (const float*)d_in[2];
    const float* brel1  = (const float*)d_in[3];
    const float* Wroot1 = (const float*)d_in[4];
    const float* gamma1 = (const float*)d_in[5];
    const float* beta1  = (const float*)d_in[6];
    const float* Wrel2  = (const float*)d_in[7];
    const float* brel2  = (const float*)d_in[8];
    const float* Wroot2 = (const float*)d_in[9];
    const float* gamma2 = (const float*)d_in[10];
    const float* beta2  = (const float*)d_in[11];

    const int N = in_sizes[0] / D_IN;
    const int E = in_sizes[1] / 2;

    float *agg2;
    __half *x16, *agg1h, *h1h, *r2h, *t16, *w1hT, *w2hT;
    double* stats;
    int *off, *csrc;
    cudaGetSymbolAddress((void**)&x16, g_x16);
    cudaGetSymbolAddress((void**)&agg1h, g_agg1h);
    cudaGetSymbolAddress((void**)&h1h, g_h1h);
    cudaGetSymbolAddress((void**)&r2h, g_r2h);
    cudaGetSymbolAddress((void**)&t16, g_t16);
    cudaGetSymbolAddress((void**)&agg2, g_agg2);
    cudaGetSymbolAddress((void**)&stats, g_stats);
    cudaGetSymbolAddress((void**)&w1hT, g_w1hT);
    cudaGetSymbolAddress((void**)&w2hT, g_w2hT);
    cudaGetSymbolAddress((void**)&off, g_off);
    cudaGetSymbolAddress((void**)&csrc, g_csrc);

    const int nchunks = ceil_div_i(N, SC_TILE);
    const int eblocks4 = ceil_div_i(E, 256 * 4);
    const int eblocks8 = ceil_div_i(E, 256 * 8);
    const float invM = 1.0f / (float)N;

    static cudaStream_t s2 = nullptr;
    static cudaEvent_t evStart = nullptr, evJoin = nullptr;
    if (!s2) {
        cudaStreamCreateWithFlags(&s2, cudaStreamNonBlocking);
        cudaEventCreateWithFlags(&evStart, cudaEventDisableTiming);
        cudaEventCreateWithFlags(&evJoin, cudaEventDisableTiming);
    }

    // ---- fork: CSR chain on main, data-prep chain on s2 ----
    cudaEventRecord(evStart, 0);
    cudaStreamWaitEvent(s2, evStart, 0);

    init_kernel<<<1024, 256, 0, s2>>>(stats, x, x16, (long long)N * D_IN / 2,
                                      Wrel1, Wroot1, Wrel2, Wroot2, w1hT, w2hT);
    cudaEventRecord(evJoin, s2);

    zero_off_kernel<<<128, 256>>>((const int*)ei, E, off, N);
    hist_kernel<<<eblocks8, 256>>>(ei, E, off);
    scan_pub_kernel<<<nchunks, SC_T>>>(off, N);
    fill_kernel<<<eblocks4, 256>>>(ei, E, off, csrc);

    // ---- join ----
    cudaStreamWaitEvent(0, evJoin, 0);
    gather1_kernel<<<ceil_div_i(N * 16, 256), 256>>>(x16, off, csrc, agg1h, N);
    gemm1_kernel<<<ceil_div_i(N, 128), 256>>>(
        agg1h, x16, w1hT, brel1, h1h, N, stats, stats + 128);

    gemm2_kernel<<<ceil_div_i(N, 128), 256>>>(h1h, w2hT, r2h, t16, N,
                                              stats, gamma1, beta1, invM);
    gather2_fused_kernel<<<ceil_div_i(N * 4, 256), 256>>>(
        t16, off, csrc, r2h, brel2, agg2, N, stats + 256, stats + 288);

    bn_relu4_kernel<<<1024, 256>>>((const float4*)agg2, (float4*)d_out,
                                   (long long)N * D_OUT / 4,
                                   stats + 256, gamma2, beta2, invM);
}